// round 1
// baseline (speedup 1.0000x reference)
#include <cuda_runtime.h>

#define BB    32
#define DIMS  8
#define DEG   32
#define P     4
#define TPB   256

__device__ __forceinline__ float ex2f(float x) {
    float r;
    asm("ex2.approx.f32 %0, %1;" : "=f"(r) : "f"(x));
    return r;
}

__global__ __launch_bounds__(TPB) void basis_kernel(
    const float* __restrict__ weights,    // (B, DIMS, DEG)
    const float* __restrict__ positions,  // (B, N)
    float* __restrict__ out,              // (B, N, DIMS) [+ zeros half]
    int N, int write_zeros)
{
    __shared__ float sw[DIMS * DEG];      // 256 floats = one batch's weights
    const int b     = blockIdx.y;
    const int chunk = blockIdx.x;
    const int tid   = threadIdx.x;

    // One cooperative load: TPB == DIMS*DEG == 256
    sw[tid] = weights[b * DIMS * DEG + tid];
    __syncthreads();

    const int n0 = chunk * (TPB * P) + tid * P;

    // 4 contiguous positions per thread (one float4 load)
    const float4 xv = *reinterpret_cast<const float4*>(positions + (size_t)b * N + n0);
    float x[P] = {xv.x, xv.y, xv.z, xv.w};

    float acc[P][DIMS];
#pragma unroll
    for (int p = 0; p < P; p++)
#pragma unroll
        for (int d = 0; d < DIMS; d++)
            acc[p][d] = 0.0f;

    // centers = linspace(0, 1.01, 32) -> step = 1.01/31
    const float step = 1.01f / 31.0f;
    // exp(-(dd^2)/(2*0.04)) = ex2(dd^2 * (-12.5 * log2(e)))
    const float NEGK = -12.5f * 1.44269504088896340736f;

#pragma unroll
    for (int g = 0; g < DEG; g++) {
        const float c = (float)g * step;
        float e[P];
#pragma unroll
        for (int p = 0; p < P; p++) {
            float dd = x[p] - c;
            e[p] = ex2f(dd * dd * NEGK);
        }
#pragma unroll
        for (int d = 0; d < DIMS; d++) {
            const float w = sw[d * DEG + g];   // broadcast LDS, amortized over P
#pragma unroll
            for (int p = 0; p < P; p++)
                acc[p][d] = fmaf(e[p], w, acc[p][d]);
        }
    }

    const size_t base = ((size_t)b * N + n0) * DIMS;
#pragma unroll
    for (int p = 0; p < P; p++) {
        float4 v0 = {acc[p][0], acc[p][1], acc[p][2], acc[p][3]};
        float4 v1 = {acc[p][4], acc[p][5], acc[p][6], acc[p][7]};
        *reinterpret_cast<float4*>(out + base + (size_t)p * DIMS)     = v0;
        *reinterpret_cast<float4*>(out + base + (size_t)p * DIMS + 4) = v1;
    }

    if (write_zeros) {
        const size_t R = (size_t)gridDim.y * (size_t)N * DIMS;
        const float4 z = {0.0f, 0.0f, 0.0f, 0.0f};
#pragma unroll
        for (int p = 0; p < P; p++) {
            *reinterpret_cast<float4*>(out + R + base + (size_t)p * DIMS)     = z;
            *reinterpret_cast<float4*>(out + R + base + (size_t)p * DIMS + 4) = z;
        }
    }
}

extern "C" void kernel_launch(void* const* d_in, const int* in_sizes, int n_in,
                              void* d_out, int out_size)
{
    // metadata order: weights (B,DIMS,DEG), weights_std (unused), positions (B,N)
    const float* weights   = (const float*)d_in[0];
    const float* positions = (const float*)d_in[2];
    float* out = (float*)d_out;

    const int N = in_sizes[2] / BB;                 // 65536
    const long long R = (long long)BB * N * DIMS;   // result element count
    const int write_zeros = (out_size >= 2 * R) ? 1 : 0;

    dim3 grid(N / (TPB * P), BB);   // (64, 32) = 2048 blocks
    basis_kernel<<<grid, TPB>>>(weights, positions, out, N, write_zeros);
}